// round 2
// baseline (speedup 1.0000x reference)
#include <cuda_runtime.h>

// 2-layer LSTM, B=2048 T=2048 H1=36 H2=1, fp32.
// 1 warp per 2 sequences (A,B); 1024 single-warp blocks.
// L1 gates (144 -> padded 160): lane owns slots {lane+32k, k=0..4}.
// W_hh1 stored transposed in smem: Wt[j][slot] -> conflict-free lane loads.

#define FULLMASK 0xffffffffu
#define H1C 36
#define G1C 144
#define GPAD 160
#define TT 2048

__device__ __forceinline__ float sigm(float x) {
    return __fdividef(1.0f, 1.0f + __expf(-x));
}
__device__ __forceinline__ float tanh_fast(float x) {
    float a = fabsf(x);
    float e = __expf(2.0f * a);                  // inf ok
    float r = 1.0f - __fdividef(2.0f, e + 1.0f); // -> 1 when e=inf
    return copysignf(r, x);
}

struct Smem {
    float  Wt[H1C][GPAD];   // Wt[j][g] = W_hh1[g][j] (pad = 0)
    float  wih[GPAD];
    float  bsum[GPAD];      // b_ih1 + b_hh1
    float  w2[H1C][4];      // w2[j][q] = W_ih2[q][j]
    float  b2[4];
    float  whh2[4];
    float2 h[H1C];          // (hA, hB)
    float2 hr[H1C];         // relu(h)
    float2 gates[GPAD];
};

__global__ void __launch_bounds__(32)
lstm2_kernel(const float* __restrict__ x,
             const float* __restrict__ W_ih1, const float* __restrict__ W_hh1,
             const float* __restrict__ b_ih1, const float* __restrict__ b_hh1,
             const float* __restrict__ W_ih2, const float* __restrict__ W_hh2,
             const float* __restrict__ b_ih2, const float* __restrict__ b_hh2,
             float* __restrict__ out)
{
    __shared__ Smem sm;
    const int lane = threadIdx.x;
    const int seqA = blockIdx.x * 2;
    const int seqB = seqA + 1;

    for (int i = lane; i < H1C * GPAD; i += 32) {
        int j = i / GPAD, s = i % GPAD;
        sm.Wt[j][s] = (s < G1C) ? W_hh1[s * H1C + j] : 0.0f;
    }
    for (int s = lane; s < GPAD; s += 32) {
        sm.wih[s]  = (s < G1C) ? W_ih1[s] : 0.0f;
        sm.bsum[s] = (s < G1C) ? (b_ih1[s] + b_hh1[s]) : 0.0f;
    }
    for (int i = lane; i < H1C * 4; i += 32) {
        int j = i >> 2, q = i & 3;
        sm.w2[j][q] = W_ih2[q * H1C + j];
    }
    if (lane < 4) {
        sm.b2[lane]   = b_ih2[lane] + b_hh2[lane];
        sm.whh2[lane] = W_hh2[lane];
    }
    for (int j = lane; j < H1C; j += 32) {
        sm.h[j]  = make_float2(0.f, 0.f);
        sm.hr[j] = make_float2(0.f, 0.f);
    }
    __syncthreads();

    const float* xA = x   + (size_t)seqA * TT;
    const float* xB = x   + (size_t)seqB * TT;
    float*       oA = out + (size_t)seqA * TT;
    float*       oB = out + (size_t)seqB * TT;

    float cA = 0.f, cB = 0.f, cA2 = 0.f, cB2 = 0.f;       // L1 cell state
    float l2cA = 0.f, l2cB = 0.f, l2hA = 0.f, l2hB = 0.f; // L2 state (replicated)
    float xbufA = 0.f, xbufB = 0.f, obufA = 0.f, obufB = 0.f;

    for (int t = 0; t < TT; ++t) {
        const int tm = t & 31;
        if (tm == 0) { xbufA = xA[t + lane]; xbufB = xB[t + lane]; }
        const float xa = __shfl_sync(FULLMASK, xbufA, tm);
        const float xb = __shfl_sync(FULLMASK, xbufB, tm);

        // ---- L1 gate preactivations
        float accA[5], accB[5];
        #pragma unroll
        for (int k = 0; k < 5; ++k) {
            float w = sm.wih[lane + 32 * k];
            float b = sm.bsum[lane + 32 * k];
            accA[k] = fmaf(xa, w, b);
            accB[k] = fmaf(xb, w, b);
        }
        #pragma unroll
        for (int j = 0; j < H1C; ++j) {
            float2 hh = sm.h[j];                       // broadcast
            #pragma unroll
            for (int k = 0; k < 5; ++k) {
                float w = sm.Wt[j][lane + 32 * k];     // conflict-free
                accA[k] = fmaf(w, hh.x, accA[k]);
                accB[k] = fmaf(w, hh.y, accB[k]);
            }
        }
        #pragma unroll
        for (int k = 0; k < 5; ++k)
            sm.gates[lane + 32 * k] = make_float2(accA[k], accB[k]);
        __syncwarp();

        // ---- L1 cell/hidden update (gate order i,f,g,o), unit = lane (+32+lane for lane<4)
        {
            float2 gi = sm.gates[lane];
            float2 gf = sm.gates[H1C + lane];
            float2 gg = sm.gates[2 * H1C + lane];
            float2 go = sm.gates[3 * H1C + lane];
            float iA = sigm(gi.x), fA = sigm(gf.x), tA = tanh_fast(gg.x), oAx = sigm(go.x);
            cA = fmaf(fA, cA, iA * tA);
            float hA = oAx * tanh_fast(cA);
            float iB = sigm(gi.y), fB = sigm(gf.y), tB = tanh_fast(gg.y), oBx = sigm(go.y);
            cB = fmaf(fB, cB, iB * tB);
            float hB = oBx * tanh_fast(cB);
            sm.h[lane]  = make_float2(hA, hB);
            sm.hr[lane] = make_float2(fmaxf(hA, 0.f), fmaxf(hB, 0.f));
        }
        if (lane < 4) {
            int u = 32 + lane;
            float2 gi = sm.gates[u];
            float2 gf = sm.gates[H1C + u];
            float2 gg = sm.gates[2 * H1C + u];
            float2 go = sm.gates[3 * H1C + u];
            float iA = sigm(gi.x), fA = sigm(gf.x), tA = tanh_fast(gg.x), oAx = sigm(go.x);
            cA2 = fmaf(fA, cA2, iA * tA);
            float hA = oAx * tanh_fast(cA2);
            float iB = sigm(gi.y), fB = sigm(gf.y), tB = tanh_fast(gg.y), oBx = sigm(go.y);
            cB2 = fmaf(fB, cB2, iB * tB);
            float hB = oBx * tanh_fast(cB2);
            sm.h[u]  = make_float2(hA, hB);
            sm.hr[u] = make_float2(fmaxf(hA, 0.f), fmaxf(hB, 0.f));
        }
        __syncwarp();

        // ---- L2 (H2=1): gate q = lane&3, partials over j = (lane>>2)+8m
        const int q  = lane & 3;
        const int j0 = lane >> 2;
        float sA = 0.f, sB = 0.f;
        #pragma unroll
        for (int m = 0; m < 4; ++m) {
            int j = j0 + 8 * m;
            float  w  = sm.w2[j][q];
            float2 hh = sm.hr[j];
            sA = fmaf(w, hh.x, sA);
            sB = fmaf(w, hh.y, sB);
        }
        if (j0 < 4) {
            int j = j0 + 32;
            float  w  = sm.w2[j][q];
            float2 hh = sm.hr[j];
            sA = fmaf(w, hh.x, sA);
            sB = fmaf(w, hh.y, sB);
        }
        #pragma unroll
        for (int off = 4; off <= 16; off <<= 1) {
            sA += __shfl_xor_sync(FULLMASK, sA, off);
            sB += __shfl_xor_sync(FULLMASK, sB, off);
        }
        float gAv = sA + sm.b2[q] + sm.whh2[q] * l2hA;
        float gBv = sB + sm.b2[q] + sm.whh2[q] * l2hB;
        const int base = lane & ~3;
        float giA = __shfl_sync(FULLMASK, gAv, base + 0);
        float gfA = __shfl_sync(FULLMASK, gAv, base + 1);
        float ggA = __shfl_sync(FULLMASK, gAv, base + 2);
        float goA = __shfl_sync(FULLMASK, gAv, base + 3);
        float giB = __shfl_sync(FULLMASK, gBv, base + 0);
        float gfB = __shfl_sync(FULLMASK, gBv, base + 1);
        float ggB = __shfl_sync(FULLMASK, gBv, base + 2);
        float goB = __shfl_sync(FULLMASK, gBv, base + 3);

        float i2A = sigm(giA), f2A = sigm(gfA), t2A = tanh_fast(ggA), o2A = sigm(goA);
        l2cA = fmaf(f2A, l2cA, i2A * t2A);
        l2hA = o2A * tanh_fast(l2cA);
        float i2B = sigm(giB), f2B = sigm(gfB), t2B = tanh_fast(ggB), o2B = sigm(goB);
        l2cB = fmaf(f2B, l2cB, i2B * t2B);
        l2hB = o2B * tanh_fast(l2cB);

        obufA = (tm == lane) ? l2hA : obufA;
        obufB = (tm == lane) ? l2hB : obufB;
        if (tm == 31) {
            oA[t - 31 + lane] = obufA;
            oB[t - 31 + lane] = obufB;
        }
    }
}

extern "C" void kernel_launch(void* const* d_in, const int* in_sizes, int n_in,
                              void* d_out, int out_size)
{
    const float* x     = (const float*)d_in[0];
    const float* W_ih1 = (const float*)d_in[1];
    const float* W_hh1 = (const float*)d_in[2];
    const float* b_ih1 = (const float*)d_in[3];
    const float* b_hh1 = (const float*)d_in[4];
    const float* W_ih2 = (const float*)d_in[5];
    const float* W_hh2 = (const float*)d_in[6];
    const float* b_ih2 = (const float*)d_in[7];
    const float* b_hh2 = (const float*)d_in[8];

    const int B = in_sizes[0] / TT;  // x is [B, T, 1]
    lstm2_kernel<<<B / 2, 32>>>(x, W_ih1, W_hh1, b_ih1, b_hh1,
                                W_ih2, W_hh2, b_ih2, b_hh2,
                                (float*)d_out);
}

// round 3
// speedup vs baseline: 1.2394x; 1.2394x over previous
#include <cuda_runtime.h>

// 2-layer LSTM, B=2048 T=2048 H1=36 H2=1, fp32.
// 1 warp per 2 sequences (A,B); 1024 single-warp blocks.
// L1 gates (144 -> padded 160): lane owns slots {lane+32k, k=0..4}.
// R2: W_hh1 held in REGISTERS (180/lane); gate MACs via packed fma.rn.f32x2.

#define FULLMASK 0xffffffffu
#define H1C 36
#define G1C 144
#define GPAD 160
#define TT 2048

__device__ __forceinline__ float2 ffma2(float2 a, float2 b, float2 c) {
    float2 d;
    asm("fma.rn.f32x2 %0, %1, %2, %3;"
        : "=l"(reinterpret_cast<unsigned long long&>(d))
        : "l"(reinterpret_cast<unsigned long long&>(a)),
          "l"(reinterpret_cast<unsigned long long&>(b)),
          "l"(reinterpret_cast<unsigned long long&>(c)));
    return d;
}

__device__ __forceinline__ float sigm(float x) {
    return __fdividef(1.0f, 1.0f + __expf(-x));
}
__device__ __forceinline__ float tanh_fast(float x) {
    float a = fabsf(x);
    float e = __expf(2.0f * a);                  // inf ok
    float r = 1.0f - __fdividef(2.0f, e + 1.0f); // -> 1 when e=inf
    return copysignf(r, x);
}

struct Smem {
    float  Wt[H1C][GPAD];   // staging only: Wt[j][g] = W_hh1[g][j] (pad = 0)
    float  wih[GPAD];
    float  bsum[GPAD];      // b_ih1 + b_hh1
    float  w2[H1C][4];      // w2[j][q] = W_ih2[q][j]
    float  b2[4];
    float  whh2[4];
    float2 h[H1C];          // (hA, hB)
    float2 hr[H1C];         // relu(h)
    float2 gates[GPAD];
};

__global__ void __launch_bounds__(32)
lstm2_kernel(const float* __restrict__ x,
             const float* __restrict__ W_ih1, const float* __restrict__ W_hh1,
             const float* __restrict__ b_ih1, const float* __restrict__ b_hh1,
             const float* __restrict__ W_ih2, const float* __restrict__ W_hh2,
             const float* __restrict__ b_ih2, const float* __restrict__ b_hh2,
             float* __restrict__ out)
{
    __shared__ Smem sm;
    const int lane = threadIdx.x;
    const int seqA = blockIdx.x * 2;
    const int seqB = seqA + 1;

    // ---- stage weights into smem (coalesced), then lift W into registers ----
    for (int i = lane; i < H1C * GPAD; i += 32) {
        int j = i / GPAD, s = i % GPAD;
        sm.Wt[j][s] = (s < G1C) ? W_hh1[s * H1C + j] : 0.0f;
    }
    for (int s = lane; s < GPAD; s += 32) {
        sm.wih[s]  = (s < G1C) ? W_ih1[s] : 0.0f;
        sm.bsum[s] = (s < G1C) ? (b_ih1[s] + b_hh1[s]) : 0.0f;
    }
    for (int i = lane; i < H1C * 4; i += 32) {
        int j = i >> 2, q = i & 3;
        sm.w2[j][q] = W_ih2[q * H1C + j];
    }
    if (lane < 4) {
        sm.b2[lane]   = b_ih2[lane] + b_hh2[lane];
        sm.whh2[lane] = W_hh2[lane];
    }
    for (int j = lane; j < H1C; j += 32) {
        sm.h[j]  = make_float2(0.f, 0.f);
        sm.hr[j] = make_float2(0.f, 0.f);
    }
    __syncthreads();

    // Register-resident W_hh1: lane's slots s_k = lane + 32k, pairs (s0,s1),(s2,s3), single s4.
    float2 W01[H1C], W23[H1C];
    float  W4[H1C];
    #pragma unroll
    for (int j = 0; j < H1C; ++j) {
        W01[j] = make_float2(sm.Wt[j][lane],      sm.Wt[j][lane + 32]);
        W23[j] = make_float2(sm.Wt[j][lane + 64], sm.Wt[j][lane + 96]);
        W4[j]  = sm.Wt[j][lane + 128];
    }
    const float2 wihP01  = make_float2(sm.wih[lane],       sm.wih[lane + 32]);
    const float2 wihP23  = make_float2(sm.wih[lane + 64],  sm.wih[lane + 96]);
    const float  wih4    = sm.wih[lane + 128];
    const float2 bsumP01 = make_float2(sm.bsum[lane],      sm.bsum[lane + 32]);
    const float2 bsumP23 = make_float2(sm.bsum[lane + 64], sm.bsum[lane + 96]);
    const float  bsum4   = sm.bsum[lane + 128];

    const float* xA = x   + (size_t)seqA * TT;
    const float* xB = x   + (size_t)seqB * TT;
    float*       oA = out + (size_t)seqA * TT;
    float*       oB = out + (size_t)seqB * TT;

    float cA = 0.f, cB = 0.f, cA2 = 0.f, cB2 = 0.f;       // L1 cell state
    float l2cA = 0.f, l2cB = 0.f, l2hA = 0.f, l2hB = 0.f; // L2 state (replicated)
    float xbufA = 0.f, xbufB = 0.f, obufA = 0.f, obufB = 0.f;

    for (int t = 0; t < TT; ++t) {
        const int tm = t & 31;
        if (tm == 0) { xbufA = xA[t + lane]; xbufB = xB[t + lane]; }
        const float xa = __shfl_sync(FULLMASK, xbufA, tm);
        const float xb = __shfl_sync(FULLMASK, xbufB, tm);

        // ---- L1 gate preactivations (register W, packed f32x2 MACs)
        const float2 xaP = make_float2(xa, xa);
        const float2 xbP = make_float2(xb, xb);
        float2 accA01 = ffma2(xaP, wihP01, bsumP01);
        float2 accA23 = ffma2(xaP, wihP23, bsumP23);
        float2 accB01 = ffma2(xbP, wihP01, bsumP01);
        float2 accB23 = ffma2(xbP, wihP23, bsumP23);
        float  accA4  = fmaf(xa, wih4, bsum4);
        float  accB4  = fmaf(xb, wih4, bsum4);

        #pragma unroll
        for (int j = 0; j < H1C; ++j) {
            float2 hh = sm.h[j];                         // broadcast LDS.64
            float2 hAA = make_float2(hh.x, hh.x);
            float2 hBB = make_float2(hh.y, hh.y);
            accA01 = ffma2(W01[j], hAA, accA01);
            accA23 = ffma2(W23[j], hAA, accA23);
            accB01 = ffma2(W01[j], hBB, accB01);
            accB23 = ffma2(W23[j], hBB, accB23);
            accA4  = fmaf(W4[j], hh.x, accA4);
            accB4  = fmaf(W4[j], hh.y, accB4);
        }
        sm.gates[lane]       = make_float2(accA01.x, accB01.x);
        sm.gates[lane + 32]  = make_float2(accA01.y, accB01.y);
        sm.gates[lane + 64]  = make_float2(accA23.x, accB23.x);
        sm.gates[lane + 96]  = make_float2(accA23.y, accB23.y);
        sm.gates[lane + 128] = make_float2(accA4,    accB4);
        __syncwarp();

        // ---- L1 cell/hidden update (gate order i,f,g,o), unit = lane (+32+lane for lane<4)
        {
            float2 gi = sm.gates[lane];
            float2 gf = sm.gates[H1C + lane];
            float2 gg = sm.gates[2 * H1C + lane];
            float2 go = sm.gates[3 * H1C + lane];
            float iA = sigm(gi.x), fA = sigm(gf.x), tA = tanh_fast(gg.x), oAx = sigm(go.x);
            cA = fmaf(fA, cA, iA * tA);
            float hA = oAx * tanh_fast(cA);
            float iB = sigm(gi.y), fB = sigm(gf.y), tB = tanh_fast(gg.y), oBx = sigm(go.y);
            cB = fmaf(fB, cB, iB * tB);
            float hB = oBx * tanh_fast(cB);
            sm.h[lane]  = make_float2(hA, hB);
            sm.hr[lane] = make_float2(fmaxf(hA, 0.f), fmaxf(hB, 0.f));
        }
        if (lane < 4) {
            int u = 32 + lane;
            float2 gi = sm.gates[u];
            float2 gf = sm.gates[H1C + u];
            float2 gg = sm.gates[2 * H1C + u];
            float2 go = sm.gates[3 * H1C + u];
            float iA = sigm(gi.x), fA = sigm(gf.x), tA = tanh_fast(gg.x), oAx = sigm(go.x);
            cA2 = fmaf(fA, cA2, iA * tA);
            float hA = oAx * tanh_fast(cA2);
            float iB = sigm(gi.y), fB = sigm(gf.y), tB = tanh_fast(gg.y), oBx = sigm(go.y);
            cB2 = fmaf(fB, cB2, iB * tB);
            float hB = oBx * tanh_fast(cB2);
            sm.h[u]  = make_float2(hA, hB);
            sm.hr[u] = make_float2(fmaxf(hA, 0.f), fmaxf(hB, 0.f));
        }
        __syncwarp();

        // ---- L2 (H2=1): gate q = lane&3, partials over j = (lane>>2)+8m
        const int q  = lane & 3;
        const int j0 = lane >> 2;
        float sA = 0.f, sB = 0.f;
        #pragma unroll
        for (int m = 0; m < 4; ++m) {
            int j = j0 + 8 * m;
            float  w  = sm.w2[j][q];
            float2 hh = sm.hr[j];
            sA = fmaf(w, hh.x, sA);
            sB = fmaf(w, hh.y, sB);
        }
        if (j0 < 4) {
            int j = j0 + 32;
            float  w  = sm.w2[j][q];
            float2 hh = sm.hr[j];
            sA = fmaf(w, hh.x, sA);
            sB = fmaf(w, hh.y, sB);
        }
        #pragma unroll
        for (int off = 4; off <= 16; off <<= 1) {
            sA += __shfl_xor_sync(FULLMASK, sA, off);
            sB += __shfl_xor_sync(FULLMASK, sB, off);
        }
        float gAv = sA + sm.b2[q] + sm.whh2[q] * l2hA;
        float gBv = sB + sm.b2[q] + sm.whh2[q] * l2hB;
        const int base = lane & ~3;
        float giA = __shfl_sync(FULLMASK, gAv, base + 0);
        float gfA = __shfl_sync(FULLMASK, gAv, base + 1);
        float ggA = __shfl_sync(FULLMASK, gAv, base + 2);
        float goA = __shfl_sync(FULLMASK, gAv, base + 3);
        float giB = __shfl_sync(FULLMASK, gBv, base + 0);
        float gfB = __shfl_sync(FULLMASK, gBv, base + 1);
        float ggB = __shfl_sync(FULLMASK, gBv, base + 2);
        float goB = __shfl_sync(FULLMASK, gBv, base + 3);

        float i2A = sigm(giA), f2A = sigm(gfA), t2A = tanh_fast(ggA), o2A = sigm(goA);
        l2cA = fmaf(f2A, l2cA, i2A * t2A);
        l2hA = o2A * tanh_fast(l2cA);
        float i2B = sigm(giB), f2B = sigm(gfB), t2B = tanh_fast(ggB), o2B = sigm(goB);
        l2cB = fmaf(f2B, l2cB, i2B * t2B);
        l2hB = o2B * tanh_fast(l2cB);

        obufA = (tm == lane) ? l2hA : obufA;
        obufB = (tm == lane) ? l2hB : obufB;
        if (tm == 31) {
            oA[t - 31 + lane] = obufA;
            oB[t - 31 + lane] = obufB;
        }
    }
}

extern "C" void kernel_launch(void* const* d_in, const int* in_sizes, int n_in,
                              void* d_out, int out_size)
{
    const float* x     = (const float*)d_in[0];
    const float* W_ih1 = (const float*)d_in[1];
    const float* W_hh1 = (const float*)d_in[2];
    const float* b_ih1 = (const float*)d_in[3];
    const float* b_hh1 = (const float*)d_in[4];
    const float* W_ih2 = (const float*)d_in[5];
    const float* W_hh2 = (const float*)d_in[6];
    const float* b_ih2 = (const float*)d_in[7];
    const float* b_hh2 = (const float*)d_in[8];

    const int B = in_sizes[0] / TT;  // x is [B, T, 1]
    lstm2_kernel<<<B / 2, 32>>>(x, W_ih1, W_hh1, b_ih1, b_hh1,
                                W_ih2, W_hh2, b_ih2, b_hh2,
                                (float*)d_out);
}

// round 4
// speedup vs baseline: 1.5179x; 1.2247x over previous
#include <cuda_runtime.h>

// 2-layer LSTM, B=2048 T=2048 H1=36 H2=1, fp32.
// 1 warp per 2 sequences (A,B); 1024 single-warp blocks.
// R3: gate slots remapped unit-major (lane l owns all 4 gates of unit l ->
//     activations straight from registers, no gate smem round-trip);
//     tanh.approx.f32 activations (1 MUFU each); 2-deep h prefetch;
//     L2(t-1) interleaved into step t's L1 work.

#define FULLMASK 0xffffffffu
#define H1C 36
#define G1C 144
#define GPAD 160
#define TT 2048

__device__ __forceinline__ float2 ffma2(float2 a, float2 b, float2 c) {
    float2 d;
    asm("fma.rn.f32x2 %0, %1, %2, %3;"
        : "=l"(reinterpret_cast<unsigned long long&>(d))
        : "l"(reinterpret_cast<unsigned long long&>(a)),
          "l"(reinterpret_cast<unsigned long long&>(b)),
          "l"(reinterpret_cast<unsigned long long&>(c)));
    return d;
}

__device__ __forceinline__ float tanha(float x) {
    float y;
    asm("tanh.approx.f32 %0, %1;" : "=f"(y) : "f"(x));
    return y;
}
__device__ __forceinline__ float sigm(float x) {
    return fmaf(0.5f, tanha(0.5f * x), 0.5f);
}

// slot s -> original gate row r (gate order i,f,g,o; 144 real rows)
__device__ __forceinline__ int slot_row(int s) {
    if (s < 128) return (s >> 5) * H1C + (s & 31);       // gate g of unit (s&31)
    int q = s - 128;                                      // units 32..35
    return (q >> 2) * H1C + 32 + (q & 3);                 // gate (q>>2) of unit 32+(q&3)
}

struct Smem {
    float  Wt[H1C][GPAD];   // staging: Wt[j][s] = W_hh1[slot_row(s)][j] (pad 0)
    float  wih[GPAD];
    float  bsum[GPAD];
    float  w2[H1C][4];      // w2[j][q] = W_ih2[q][j]
    float  b2[4];
    float  whh2[4];
    float2 h[H1C];          // (hA, hB)
    float2 hr[H1C];         // relu(h)
};

__global__ void __launch_bounds__(32)
lstm2_kernel(const float* __restrict__ x,
             const float* __restrict__ W_ih1, const float* __restrict__ W_hh1,
             const float* __restrict__ b_ih1, const float* __restrict__ b_hh1,
             const float* __restrict__ W_ih2, const float* __restrict__ W_hh2,
             const float* __restrict__ b_ih2, const float* __restrict__ b_hh2,
             float* __restrict__ out)
{
    __shared__ Smem sm;
    const int lane = threadIdx.x;
    const int seqA = blockIdx.x * 2;

    // ---- stage weights (remapped slots) ----
    for (int i = lane; i < H1C * GPAD; i += 32) {
        int j = i / GPAD, s = i % GPAD;
        sm.Wt[j][s] = (s < G1C) ? W_hh1[slot_row(s) * H1C + j] : 0.0f;
    }
    for (int s = lane; s < GPAD; s += 32) {
        if (s < G1C) {
            int r = slot_row(s);
            sm.wih[s]  = W_ih1[r];
            sm.bsum[s] = b_ih1[r] + b_hh1[r];
        } else { sm.wih[s] = 0.0f; sm.bsum[s] = 0.0f; }
    }
    for (int i = lane; i < H1C * 4; i += 32) {
        int j = i >> 2, q = i & 3;
        sm.w2[j][q] = W_ih2[q * H1C + j];
    }
    if (lane < 4) {
        sm.b2[lane]   = b_ih2[lane] + b_hh2[lane];
        sm.whh2[lane] = W_hh2[lane];
    }
    for (int j = lane; j < H1C; j += 32) {
        sm.h[j]  = make_float2(0.f, 0.f);
        sm.hr[j] = make_float2(0.f, 0.f);
    }
    __syncthreads();

    // ---- lift W into registers: lane slots (l, l+32)=(i,f), (l+64,l+96)=(g,o), l+128=extra
    float2 W01[H1C], W23[H1C];
    float  W4[H1C];
    #pragma unroll
    for (int j = 0; j < H1C; ++j) {
        W01[j] = make_float2(sm.Wt[j][lane],      sm.Wt[j][lane + 32]);
        W23[j] = make_float2(sm.Wt[j][lane + 64], sm.Wt[j][lane + 96]);
        W4[j]  = sm.Wt[j][lane + 128];
    }
    const float2 wihP01  = make_float2(sm.wih[lane],       sm.wih[lane + 32]);
    const float2 wihP23  = make_float2(sm.wih[lane + 64],  sm.wih[lane + 96]);
    const float  wih4    = sm.wih[lane + 128];
    const float2 bsumP01 = make_float2(sm.bsum[lane],      sm.bsum[lane + 32]);
    const float2 bsumP23 = make_float2(sm.bsum[lane + 64], sm.bsum[lane + 96]);
    const float  bsum4   = sm.bsum[lane + 128];
    const int    q   = lane & 3;
    const float  b2q = sm.b2[q];
    const float  whq = sm.whh2[q];

    const float* xA = x   + (size_t)seqA * TT;
    const float* xB = xA + TT;
    float*       oA = out + (size_t)seqA * TT;
    float*       oB = oA + TT;

    float cA = 0.f, cB = 0.f, cA2 = 0.f, cB2 = 0.f;
    float l2cA = 0.f, l2cB = 0.f, l2hA = 0.f, l2hB = 0.f;
    float xbufA = 0.f, xbufB = 0.f, obufA = 0.f, obufB = 0.f;

    // L2 for step tp (reads sm.hr holding step-tp values)
    auto do_l2 = [&](int tp) {
        const int j0 = lane >> 2;
        float sA = 0.f, sB = 0.f;
        #pragma unroll
        for (int m = 0; m < 4; ++m) {
            int j = j0 + 8 * m;
            float  w  = sm.w2[j][q];
            float2 hh = sm.hr[j];
            sA = fmaf(w, hh.x, sA);
            sB = fmaf(w, hh.y, sB);
        }
        if (j0 < 4) {
            int j = j0 + 32;
            float  w  = sm.w2[j][q];
            float2 hh = sm.hr[j];
            sA = fmaf(w, hh.x, sA);
            sB = fmaf(w, hh.y, sB);
        }
        #pragma unroll
        for (int off = 4; off <= 16; off <<= 1) {
            sA += __shfl_xor_sync(FULLMASK, sA, off);
            sB += __shfl_xor_sync(FULLMASK, sB, off);
        }
        float gAv = sA + b2q + whq * l2hA;
        float gBv = sB + b2q + whq * l2hB;
        const int base = lane & ~3;
        float giA = __shfl_sync(FULLMASK, gAv, base + 0);
        float gfA = __shfl_sync(FULLMASK, gAv, base + 1);
        float ggA = __shfl_sync(FULLMASK, gAv, base + 2);
        float goA = __shfl_sync(FULLMASK, gAv, base + 3);
        float giB = __shfl_sync(FULLMASK, gBv, base + 0);
        float gfB = __shfl_sync(FULLMASK, gBv, base + 1);
        float ggB = __shfl_sync(FULLMASK, gBv, base + 2);
        float goB = __shfl_sync(FULLMASK, gBv, base + 3);

        l2cA = fmaf(sigm(gfA), l2cA, sigm(giA) * tanha(ggA));
        l2hA = sigm(goA) * tanha(l2cA);
        l2cB = fmaf(sigm(gfB), l2cB, sigm(giB) * tanha(ggB));
        l2hB = sigm(goB) * tanha(l2cB);

        const int tmp = tp & 31;
        obufA = (tmp == lane) ? l2hA : obufA;
        obufB = (tmp == lane) ? l2hB : obufB;
        if (tmp == 31) {
            oA[tp - 31 + lane] = obufA;
            oB[tp - 31 + lane] = obufB;
        }
    };

    for (int t = 0; t < TT; ++t) {
        const int tm = t & 31;
        if (tm == 0) { xbufA = xA[t + lane]; xbufB = xB[t + lane]; }
        const float xa = __shfl_sync(FULLMASK, xbufA, tm);
        const float xb = __shfl_sync(FULLMASK, xbufB, tm);

        // ---- L1 gate accumulation (register W, f32x2, 2-deep h prefetch)
        const float2 xaP = make_float2(xa, xa);
        const float2 xbP = make_float2(xb, xb);
        float2 accA01 = ffma2(xaP, wihP01, bsumP01);
        float2 accA23 = ffma2(xaP, wihP23, bsumP23);
        float2 accB01 = ffma2(xbP, wihP01, bsumP01);
        float2 accB23 = ffma2(xbP, wihP23, bsumP23);
        float  accA4  = fmaf(xa, wih4, bsum4);
        float  accB4  = fmaf(xb, wih4, bsum4);

        float2 h0 = sm.h[0];
        float2 h1 = sm.h[1];
        #pragma unroll
        for (int j = 0; j < H1C; ++j) {
            float2 hn = (j + 2 < H1C) ? sm.h[j + 2] : make_float2(0.f, 0.f);
            float2 hAA = make_float2(h0.x, h0.x);
            float2 hBB = make_float2(h0.y, h0.y);
            accA01 = ffma2(W01[j], hAA, accA01);
            accA23 = ffma2(W23[j], hAA, accA23);
            accB01 = ffma2(W01[j], hBB, accB01);
            accB23 = ffma2(W23[j], hBB, accB23);
            accA4  = fmaf(W4[j], h0.x, accA4);
            accB4  = fmaf(W4[j], h0.y, accB4);
            h0 = h1; h1 = hn;
        }

        // ---- L2 for previous step (independent of this step's activations;
        //      reads sm.hr before it is overwritten below -> warp-order safe)
        if (t) do_l2(t - 1);

        // ---- L1 activations straight from registers (unit = lane)
        {
            float iA = sigm(accA01.x), fA = sigm(accA01.y);
            float tA = tanha(accA23.x), oAx = sigm(accA23.y);
            cA = fmaf(fA, cA, iA * tA);
            float hA = oAx * tanha(cA);
            float iB = sigm(accB01.x), fB = sigm(accB01.y);
            float tB = tanha(accB23.x), oBx = sigm(accB23.y);
            cB = fmaf(fB, cB, iB * tB);
            float hB = oBx * tanha(cB);
            sm.h[lane]  = make_float2(hA, hB);
            sm.hr[lane] = make_float2(fmaxf(hA, 0.f), fmaxf(hB, 0.f));
        }
        // extra units 32..35: gates of unit 32+m live in lanes m+4g (k=4)
        {
            float fEA = __shfl_sync(FULLMASK, accA4, q + 4);
            float gEA = __shfl_sync(FULLMASK, accA4, q + 8);
            float oEA = __shfl_sync(FULLMASK, accA4, q + 12);
            float fEB = __shfl_sync(FULLMASK, accB4, q + 4);
            float gEB = __shfl_sync(FULLMASK, accB4, q + 8);
            float oEB = __shfl_sync(FULLMASK, accB4, q + 12);
            if (lane < 4) {
                float iA = sigm(accA4), fA = sigm(fEA);
                float tA = tanha(gEA), oAx = sigm(oEA);
                cA2 = fmaf(fA, cA2, iA * tA);
                float hA = oAx * tanha(cA2);
                float iB = sigm(accB4), fB = sigm(fEB);
                float tB = tanha(gEB), oBx = sigm(oEB);
                cB2 = fmaf(fB, cB2, iB * tB);
                float hB = oBx * tanha(cB2);
                sm.h[32 + lane]  = make_float2(hA, hB);
                sm.hr[32 + lane] = make_float2(fmaxf(hA, 0.f), fmaxf(hB, 0.f));
            }
        }
        __syncwarp();
    }
    do_l2(TT - 1);   // final step's L2 + output flush
}

extern "C" void kernel_launch(void* const* d_in, const int* in_sizes, int n_in,
                              void* d_out, int out_size)
{
    const float* x     = (const float*)d_in[0];
    const float* W_ih1 = (const float*)d_in[1];
    const float* W_hh1 = (const float*)d_in[2];
    const float* b_ih1 = (const float*)d_in[3];
    const float* b_hh1 = (const float*)d_in[4];
    const float* W_ih2 = (const float*)d_in[5];
    const float* W_hh2 = (const float*)d_in[6];
    const float* b_ih2 = (const float*)d_in[7];
    const float* b_hh2 = (const float*)d_in[8];

    const int B = in_sizes[0] / TT;  // x is [B, T, 1]
    lstm2_kernel<<<B / 2, 32>>>(x, W_ih1, W_hh1, b_ih1, b_hh1,
                                W_ih2, W_hh2, b_ih2, b_hh2,
                                (float*)d_out);
}